// round 2
// baseline (speedup 1.0000x reference)
#include <cuda_runtime.h>
#include <math.h>

#define NOSC 256
#define DDIM 64
#define NSTEPS 10

// Transposed W scratch (allowed: __device__ global, no dynamic alloc)
__device__ float g_Wt[NOSC * NOSC];

__global__ void wt_transpose_kernel(const float* __restrict__ W) {
    int j = blockIdx.x;   // 256 blocks
    int i = threadIdx.x;  // 256 threads
    g_Wt[j * NOSC + i] = W[i * NOSC + j];
}

__global__ __launch_bounds__(256, 1)
void akorn_kernel(const float* __restrict__ x_in,
                  const float* __restrict__ eta_p,
                  const float* __restrict__ A,
                  const float* __restrict__ h,
                  const float* __restrict__ w_ro,
                  const float* __restrict__ b_ro,
                  float* __restrict__ out,
                  float* __restrict__ x_out,
                  int write_x)
{
    extern __shared__ float sm[];
    float* xs  = sm;                     // [256][64] oscillator state
    float* Os  = sm + NOSC * DDIM;       // [64][64]  Omega = A - A^T
    float* red = Os + DDIM * DDIM;       // [256] readout reduction

    const int b  = blockIdx.x;
    const int t  = threadIdx.x;
    const int di = t & 7;                // d-group (8 cols each)
    const int ii = t >> 3;               // i-group (8 rows each)
    const int c0 = di * 8;
    const float eta = __ldg(eta_p);

    // Build Omega in smem
    for (int idx = t; idx < DDIM * DDIM; idx += 256) {
        int e = idx >> 6, dd = idx & 63;
        Os[idx] = __ldg(&A[e * DDIM + dd]) - __ldg(&A[dd * DDIM + e]);
    }

    // Load + L2-normalize x_b into smem
    const float* xb = x_in + (size_t)b * NOSC * DDIM;
    #pragma unroll
    for (int r = 0; r < 8; r++) {
        int i = ii * 8 + r;
        float4 a0 = __ldg((const float4*)&xb[i * DDIM + c0]);
        float4 a1 = __ldg((const float4*)&xb[i * DDIM + c0 + 4]);
        float ss = a0.x*a0.x + a0.y*a0.y + a0.z*a0.z + a0.w*a0.w
                 + a1.x*a1.x + a1.y*a1.y + a1.z*a1.z + a1.w*a1.w;
        ss += __shfl_xor_sync(0xffffffffu, ss, 1, 8);
        ss += __shfl_xor_sync(0xffffffffu, ss, 2, 8);
        ss += __shfl_xor_sync(0xffffffffu, ss, 4, 8);
        float inv = 1.0f / fmaxf(sqrtf(ss), 1e-12f);
        float4 s0 = make_float4(a0.x*inv, a0.y*inv, a0.z*inv, a0.w*inv);
        float4 s1 = make_float4(a1.x*inv, a1.y*inv, a1.z*inv, a1.w*inv);
        *(float4*)&xs[i * DDIM + c0]     = s0;
        *(float4*)&xs[i * DDIM + c0 + 4] = s1;
    }
    __syncthreads();

    for (int step = 0; step < NSTEPS; step++) {
        float acc[8][8];

        // drive init: h
        #pragma unroll
        for (int r = 0; r < 8; r++) {
            int i = ii * 8 + r;
            float4 h0 = __ldg((const float4*)&h[i * DDIM + c0]);
            float4 h1 = __ldg((const float4*)&h[i * DDIM + c0 + 4]);
            acc[r][0] = h0.x; acc[r][1] = h0.y; acc[r][2] = h0.z; acc[r][3] = h0.w;
            acc[r][4] = h1.x; acc[r][5] = h1.y; acc[r][6] = h1.z; acc[r][7] = h1.w;
        }

        // natural frequency rotation: acc[r][c] += sum_k xs[i][k] * Omega[k][c0+c]
        #pragma unroll 4
        for (int k = 0; k < DDIM; k++) {
            float4 o0 = *(const float4*)&Os[k * DDIM + c0];
            float4 o1 = *(const float4*)&Os[k * DDIM + c0 + 4];
            float of[8] = {o0.x, o0.y, o0.z, o0.w, o1.x, o1.y, o1.z, o1.w};
            #pragma unroll
            for (int r = 0; r < 8; r++) {
                float xv = xs[(ii * 8 + r) * DDIM + k];
                #pragma unroll
                for (int c = 0; c < 8; c++) acc[r][c] += xv * of[c];
            }
        }

        // coupling: acc[r][c] += sum_j W[i][j] * xs[j][c0+c]  (W pre-transposed)
        #pragma unroll 2
        for (int j = 0; j < NOSC; j++) {
            float4 w0 = __ldg((const float4*)&g_Wt[j * NOSC + ii * 8]);
            float4 w1 = __ldg((const float4*)&g_Wt[j * NOSC + ii * 8 + 4]);
            float4 x0 = *(const float4*)&xs[j * DDIM + c0];
            float4 x1 = *(const float4*)&xs[j * DDIM + c0 + 4];
            float wf[8] = {w0.x, w0.y, w0.z, w0.w, w1.x, w1.y, w1.z, w1.w};
            float xf[8] = {x0.x, x0.y, x0.z, x0.w, x1.x, x1.y, x1.z, x1.w};
            #pragma unroll
            for (int r = 0; r < 8; r++)
                #pragma unroll
                for (int c = 0; c < 8; c++)
                    acc[r][c] += wf[r] * xf[c];
        }

        __syncthreads();  // all cross-thread reads of xs complete

        // tangent-space update + renormalize (thread-private elements only)
        #pragma unroll
        for (int r = 0; r < 8; r++) {
            int i = ii * 8 + r;
            float4 x0 = *(const float4*)&xs[i * DDIM + c0];
            float4 x1 = *(const float4*)&xs[i * DDIM + c0 + 4];
            float xv[8] = {x0.x, x0.y, x0.z, x0.w, x1.x, x1.y, x1.z, x1.w};
            float dp = 0.f;
            #pragma unroll
            for (int c = 0; c < 8; c++) dp += xv[c] * acc[r][c];
            dp += __shfl_xor_sync(0xffffffffu, dp, 1, 8);
            dp += __shfl_xor_sync(0xffffffffu, dp, 2, 8);
            dp += __shfl_xor_sync(0xffffffffu, dp, 4, 8);
            float nx[8]; float ss = 0.f;
            #pragma unroll
            for (int c = 0; c < 8; c++) {
                nx[c] = xv[c] + eta * (acc[r][c] - dp * xv[c]);
                ss += nx[c] * nx[c];
            }
            ss += __shfl_xor_sync(0xffffffffu, ss, 1, 8);
            ss += __shfl_xor_sync(0xffffffffu, ss, 2, 8);
            ss += __shfl_xor_sync(0xffffffffu, ss, 4, 8);
            float inv = 1.0f / fmaxf(sqrtf(ss), 1e-12f);
            *(float4*)&xs[i * DDIM + c0] =
                make_float4(nx[0]*inv, nx[1]*inv, nx[2]*inv, nx[3]*inv);
            *(float4*)&xs[i * DDIM + c0 + 4] =
                make_float4(nx[4]*inv, nx[5]*inv, nx[6]*inv, nx[7]*inv);
        }
        __syncthreads();
    }

    // Readout + write final x
    float4 wr0 = __ldg((const float4*)&w_ro[c0]);
    float4 wr1 = __ldg((const float4*)&w_ro[c0 + 4]);
    float wrf[8] = {wr0.x, wr0.y, wr0.z, wr0.w, wr1.x, wr1.y, wr1.z, wr1.w};
    float part = 0.f;
    #pragma unroll
    for (int r = 0; r < 8; r++) {
        int i = ii * 8 + r;
        float4 v0 = *(const float4*)&xs[i * DDIM + c0];
        float4 v1 = *(const float4*)&xs[i * DDIM + c0 + 4];
        part += v0.x*wrf[0] + v0.y*wrf[1] + v0.z*wrf[2] + v0.w*wrf[3]
              + v1.x*wrf[4] + v1.y*wrf[5] + v1.z*wrf[6] + v1.w*wrf[7];
        if (write_x) {
            float* xo = x_out + (size_t)b * NOSC * DDIM + i * DDIM + c0;
            *(float4*)&xo[0] = v0;
            *(float4*)&xo[4] = v1;
        }
    }
    red[t] = part;
    __syncthreads();
    #pragma unroll
    for (int s = 128; s > 0; s >>= 1) {
        if (t < s) red[t] += red[t + s];
        __syncthreads();
    }
    if (t == 0) out[b] = red[0] / (float)NOSC + __ldg(b_ro);
}

extern "C" void kernel_launch(void* const* d_in, const int* in_sizes, int n_in,
                              void* d_out, int out_size) {
    const float* x    = (const float*)d_in[0];
    const float* eta  = (const float*)d_in[1];
    const float* W    = (const float*)d_in[2];
    const float* A    = (const float*)d_in[3];
    const float* h    = (const float*)d_in[4];
    const float* w_ro = (const float*)d_in[5];
    const float* b_ro = (const float*)d_in[6];

    const int B = in_sizes[0] / (NOSC * DDIM);
    float* out = (float*)d_out;

    // Output tuple (out, x): out first (B), then x (B*N*d) if the buffer has room.
    int write_x = (out_size >= B + B * NOSC * DDIM) ? 1 : 0;
    float* x_out = out + B;

    const int smem_bytes = (NOSC * DDIM + DDIM * DDIM + 256) * (int)sizeof(float);
    cudaFuncSetAttribute(akorn_kernel,
                         cudaFuncAttributeMaxDynamicSharedMemorySize, smem_bytes);

    wt_transpose_kernel<<<NOSC, NOSC>>>(W);
    akorn_kernel<<<B, 256, smem_bytes>>>(x, eta, A, h, w_ro, b_ro,
                                         out, x_out, write_x);
}

// round 3
// speedup vs baseline: 1.0838x; 1.0838x over previous
#include <cuda_runtime.h>
#include <math.h>

#define NOSC 256
#define DDIM 64
#define NSTEPS 10

typedef unsigned long long u64;

// Transposed W scratch (allowed: __device__ global, no dynamic alloc)
__device__ float g_Wt[NOSC * NOSC];

__global__ void wt_transpose_kernel(const float* __restrict__ W) {
    int j = blockIdx.x;   // 256 blocks
    int i = threadIdx.x;  // 256 threads
    g_Wt[j * NOSC + i] = W[i * NOSC + j];
}

// ---- packed f32x2 helpers (Blackwell FFMA2 path, PTX-only) ----
__device__ __forceinline__ u64 pkd(float a) {            // (a, a)
    u64 r; asm("mov.b64 %0, {%1, %1};" : "=l"(r) : "f"(a)); return r;
}
__device__ __forceinline__ void fma2(u64& d, u64 a, u64 b) {
    asm("fma.rn.f32x2 %0, %1, %2, %0;" : "+l"(d) : "l"(a), "l"(b));
}
__device__ __forceinline__ float2 upk(u64 v) {
    float lo, hi; asm("mov.b64 {%0, %1}, %2;" : "=f"(lo), "=f"(hi) : "l"(v));
    return make_float2(lo, hi);
}

__global__ __launch_bounds__(256, 1)
void akorn_kernel(const float* __restrict__ x_in,
                  const float* __restrict__ eta_p,
                  const float* __restrict__ A,
                  const float* __restrict__ h,
                  const float* __restrict__ w_ro,
                  const float* __restrict__ b_ro,
                  float* __restrict__ out,
                  float* __restrict__ x_out,
                  int write_x)
{
    extern __shared__ float sm[];
    float* xs  = sm;                     // [256][64] oscillator state
    float* Os  = sm + NOSC * DDIM;       // [64][64]  Omega = A - A^T
    float* red = Os + DDIM * DDIM;       // [256] readout reduction

    const int b  = blockIdx.x;
    const int t  = threadIdx.x;
    const int di = t & 7;                // d-group (8 cols each)
    const int ii = t >> 3;               // i-group (8 rows each)
    const int c0 = di * 8;
    const float eta = __ldg(eta_p);

    // Build Omega in smem
    for (int idx = t; idx < DDIM * DDIM; idx += 256) {
        int e = idx >> 6, dd = idx & 63;
        Os[idx] = __ldg(&A[e * DDIM + dd]) - __ldg(&A[dd * DDIM + e]);
    }

    // Load + L2-normalize x_b into smem
    const float* xb = x_in + (size_t)b * NOSC * DDIM;
    #pragma unroll
    for (int r = 0; r < 8; r++) {
        int i = ii * 8 + r;
        float4 a0 = __ldg((const float4*)&xb[i * DDIM + c0]);
        float4 a1 = __ldg((const float4*)&xb[i * DDIM + c0 + 4]);
        float ss = a0.x*a0.x + a0.y*a0.y + a0.z*a0.z + a0.w*a0.w
                 + a1.x*a1.x + a1.y*a1.y + a1.z*a1.z + a1.w*a1.w;
        ss += __shfl_xor_sync(0xffffffffu, ss, 1, 8);
        ss += __shfl_xor_sync(0xffffffffu, ss, 2, 8);
        ss += __shfl_xor_sync(0xffffffffu, ss, 4, 8);
        float inv = 1.0f / fmaxf(sqrtf(ss), 1e-12f);
        *(float4*)&xs[i * DDIM + c0] =
            make_float4(a0.x*inv, a0.y*inv, a0.z*inv, a0.w*inv);
        *(float4*)&xs[i * DDIM + c0 + 4] =
            make_float4(a1.x*inv, a1.y*inv, a1.z*inv, a1.w*inv);
    }
    __syncthreads();

    for (int step = 0; step < NSTEPS; step++) {
        // packed accumulators: acc[r][c2] holds (drive[c0+2c2], drive[c0+2c2+1])
        u64 acc[8][4];

        // drive init: h  (memory-natural f32 pairs)
        #pragma unroll
        for (int r = 0; r < 8; r++) {
            int i = ii * 8 + r;
            ulonglong2 h0 = __ldg((const ulonglong2*)&h[i * DDIM + c0]);
            ulonglong2 h1 = __ldg((const ulonglong2*)&h[i * DDIM + c0 + 4]);
            acc[r][0] = h0.x; acc[r][1] = h0.y;
            acc[r][2] = h1.x; acc[r][3] = h1.y;
        }

        // natural frequency rotation: acc[r][*] += xs[i][k] * Omega[k][c0..]
        #pragma unroll 2
        for (int k0 = 0; k0 < DDIM; k0 += 4) {
            u64 op[4][4];
            #pragma unroll
            for (int kk = 0; kk < 4; kk++) {
                ulonglong2 oa = *(const ulonglong2*)&Os[(k0+kk) * DDIM + c0];
                ulonglong2 ob = *(const ulonglong2*)&Os[(k0+kk) * DDIM + c0 + 4];
                op[kk][0] = oa.x; op[kk][1] = oa.y;
                op[kk][2] = ob.x; op[kk][3] = ob.y;
            }
            #pragma unroll
            for (int r = 0; r < 8; r++) {
                float4 xv = *(const float4*)&xs[(ii * 8 + r) * DDIM + k0];
                u64 xd0 = pkd(xv.x), xd1 = pkd(xv.y), xd2 = pkd(xv.z), xd3 = pkd(xv.w);
                #pragma unroll
                for (int c = 0; c < 4; c++) {
                    fma2(acc[r][c], xd0, op[0][c]);
                    fma2(acc[r][c], xd1, op[1][c]);
                    fma2(acc[r][c], xd2, op[2][c]);
                    fma2(acc[r][c], xd3, op[3][c]);
                }
            }
        }

        // coupling: acc[r][*] += W[i][j] * xs[j][c0..]   (W pre-transposed)
        #pragma unroll 2
        for (int j = 0; j < NOSC; j++) {
            float4 w0 = __ldg((const float4*)&g_Wt[j * NOSC + ii * 8]);
            float4 w1 = __ldg((const float4*)&g_Wt[j * NOSC + ii * 8 + 4]);
            ulonglong2 xq0 = *(const ulonglong2*)&xs[j * DDIM + c0];
            ulonglong2 xq1 = *(const ulonglong2*)&xs[j * DDIM + c0 + 4];
            u64 xp[4] = {xq0.x, xq0.y, xq1.x, xq1.y};
            u64 wd[8] = {pkd(w0.x), pkd(w0.y), pkd(w0.z), pkd(w0.w),
                         pkd(w1.x), pkd(w1.y), pkd(w1.z), pkd(w1.w)};
            #pragma unroll
            for (int r = 0; r < 8; r++) {
                #pragma unroll
                for (int c = 0; c < 4; c++)
                    fma2(acc[r][c], wd[r], xp[c]);
            }
        }

        __syncthreads();  // all cross-thread reads of xs complete

        // tangent-space update + renormalize (thread-private elements only)
        #pragma unroll
        for (int r = 0; r < 8; r++) {
            int i = ii * 8 + r;
            float2 d0 = upk(acc[r][0]), d1 = upk(acc[r][1]);
            float2 d2 = upk(acc[r][2]), d3 = upk(acc[r][3]);
            float dv[8] = {d0.x, d0.y, d1.x, d1.y, d2.x, d2.y, d3.x, d3.y};
            float4 x0 = *(const float4*)&xs[i * DDIM + c0];
            float4 x1 = *(const float4*)&xs[i * DDIM + c0 + 4];
            float xv[8] = {x0.x, x0.y, x0.z, x0.w, x1.x, x1.y, x1.z, x1.w};
            float dp = 0.f;
            #pragma unroll
            for (int c = 0; c < 8; c++) dp += xv[c] * dv[c];
            dp += __shfl_xor_sync(0xffffffffu, dp, 1, 8);
            dp += __shfl_xor_sync(0xffffffffu, dp, 2, 8);
            dp += __shfl_xor_sync(0xffffffffu, dp, 4, 8);
            float nx[8]; float ss = 0.f;
            #pragma unroll
            for (int c = 0; c < 8; c++) {
                nx[c] = xv[c] + eta * (dv[c] - dp * xv[c]);
                ss += nx[c] * nx[c];
            }
            ss += __shfl_xor_sync(0xffffffffu, ss, 1, 8);
            ss += __shfl_xor_sync(0xffffffffu, ss, 2, 8);
            ss += __shfl_xor_sync(0xffffffffu, ss, 4, 8);
            float inv = 1.0f / fmaxf(sqrtf(ss), 1e-12f);
            *(float4*)&xs[i * DDIM + c0] =
                make_float4(nx[0]*inv, nx[1]*inv, nx[2]*inv, nx[3]*inv);
            *(float4*)&xs[i * DDIM + c0 + 4] =
                make_float4(nx[4]*inv, nx[5]*inv, nx[6]*inv, nx[7]*inv);
        }
        __syncthreads();
    }

    // Readout + write final x
    float4 wr0 = __ldg((const float4*)&w_ro[c0]);
    float4 wr1 = __ldg((const float4*)&w_ro[c0 + 4]);
    float wrf[8] = {wr0.x, wr0.y, wr0.z, wr0.w, wr1.x, wr1.y, wr1.z, wr1.w};
    float part = 0.f;
    #pragma unroll
    for (int r = 0; r < 8; r++) {
        int i = ii * 8 + r;
        float4 v0 = *(const float4*)&xs[i * DDIM + c0];
        float4 v1 = *(const float4*)&xs[i * DDIM + c0 + 4];
        part += v0.x*wrf[0] + v0.y*wrf[1] + v0.z*wrf[2] + v0.w*wrf[3]
              + v1.x*wrf[4] + v1.y*wrf[5] + v1.z*wrf[6] + v1.w*wrf[7];
        if (write_x) {
            float* xo = x_out + (size_t)b * NOSC * DDIM + i * DDIM + c0;
            *(float4*)&xo[0] = v0;
            *(float4*)&xo[4] = v1;
        }
    }
    red[t] = part;
    __syncthreads();
    #pragma unroll
    for (int s = 128; s > 0; s >>= 1) {
        if (t < s) red[t] += red[t + s];
        __syncthreads();
    }
    if (t == 0) out[b] = red[0] / (float)NOSC + __ldg(b_ro);
}

extern "C" void kernel_launch(void* const* d_in, const int* in_sizes, int n_in,
                              void* d_out, int out_size) {
    const float* x    = (const float*)d_in[0];
    const float* eta  = (const float*)d_in[1];
    const float* W    = (const float*)d_in[2];
    const float* A    = (const float*)d_in[3];
    const float* h    = (const float*)d_in[4];
    const float* w_ro = (const float*)d_in[5];
    const float* b_ro = (const float*)d_in[6];

    const int B = in_sizes[0] / (NOSC * DDIM);
    float* out = (float*)d_out;

    // Output tuple (out, x): out first (B), then x (B*N*d) if the buffer has room.
    int write_x = (out_size >= B + B * NOSC * DDIM) ? 1 : 0;
    float* x_out = out + B;

    const int smem_bytes = (NOSC * DDIM + DDIM * DDIM + 256) * (int)sizeof(float);
    cudaFuncSetAttribute(akorn_kernel,
                         cudaFuncAttributeMaxDynamicSharedMemorySize, smem_bytes);

    wt_transpose_kernel<<<NOSC, NOSC>>>(W);
    akorn_kernel<<<B, 256, smem_bytes>>>(x, eta, A, h, w_ro, b_ro,
                                         out, x_out, write_x);
}